// round 15
// baseline (speedup 1.0000x reference)
#include <cuda_runtime.h>
#include <cuda_bf16.h>
#include <cuda_fp16.h>
#include <math.h>
#include <stdint.h>

#define B_ 4096
#define M_ 4
#define D_ 512
#define N_ ((M_ + 1) * B_)   // 20480

// Static device scratch (no runtime allocation)
__device__ uint8_t g_fp8[(size_t)N_ * D_];   // normalized rows * 16, e4m3, 10 MB
__device__ float g_denom[B_];                // stores denom * 2^-8
__device__ float g_pos[B_];
__device__ int   g_tile_ctr;
__device__ int   g_done_ctr;

__device__ __forceinline__ float get_temp(int it) {
    if (it >= 300000) return 0.05f;
    float progress = (float)it / 300000.0f;
    return 0.05f + 0.5f * (0.2f - 0.05f) * (1.0f + cosf(3.14159265358979323846f * progress));
}

__device__ __forceinline__ uint32_t smem_u32(const void* p) {
    uint32_t a;
    asm("{ .reg .u64 t; cvta.to.shared.u64 t, %1; cvt.u32.u64 %0, t; }" : "=r"(a) : "l"(p));
    return a;
}

__device__ __forceinline__ uint32_t swz128(uint32_t off) {
    return off ^ ((off >> 3) & 0x70);
}

#define CP_ASYNC16(dst, src) \
    asm volatile("cp.async.cg.shared.global [%0], [%1], 16;" :: "r"(dst), "l"(src) : "memory")
#define CP_COMMIT() asm volatile("cp.async.commit_group;" ::: "memory")

#define LDMATRIX_X4(r0, r1, r2, r3, addr) \
    asm volatile("ldmatrix.sync.aligned.m8n8.x4.shared.b16 {%0,%1,%2,%3}, [%4];" \
                 : "=r"(r0), "=r"(r1), "=r"(r2), "=r"(r3) : "r"(addr))

// FP8 e4m3 inputs, F16 accumulators (2 regs = 4 packed halves)
#define MMA_FP8_H(d, a, b0, b1) \
    asm volatile("mma.sync.aligned.m16n8k32.row.col.f16.e4m3.e4m3.f16 " \
                 "{%0,%1}, {%2,%3,%4,%5}, {%6,%7}, {%0,%1};" \
                 : "+r"((d)[0]), "+r"((d)[1]) \
                 : "r"((a)[0]), "r"((a)[1]), "r"((a)[2]), "r"((a)[3]), \
                   "r"(b0), "r"(b1))

__device__ __forceinline__ uint32_t ex2_f16x2(uint32_t y) {
    uint32_t r;
    asm("ex2.approx.f16x2 %0, %1;" : "=r"(r) : "r"(y));
    return r;
}

__device__ __forceinline__ uint16_t pack_e4m3x2(float lo, float hi) {
    uint16_t r;
    asm("cvt.rn.satfinite.e4m3x2.f32 %0, %1, %2;" : "=h"(r) : "f"(hi), "f"(lo));
    return r;
}

// ---------------------------------------------------------------------------
// Kernel 1 (fused prep): 2048 blocks x 256 threads; each half-block (128 thr)
// handles one orig row: norms, exact positives, quantize 5 rows to fp8.
// Doubled per-CTA loads in flight vs 1-row blocks (prep was latency-bound).
// ---------------------------------------------------------------------------
__global__ __launch_bounds__(256) void prep_kernel(const float* __restrict__ orig,
                                                   const float* __restrict__ masked,
                                                   const int* __restrict__ d_iter) {
    const int half = threadIdx.x >> 7;            // 0/1
    const int i = blockIdx.x * 2 + half;          // orig row
    const int t = threadIdx.x & 127;              // 0..127 within half
    float4 v[5];
    v[0] = ((const float4*)(orig + (size_t)i * D_))[t];
    #pragma unroll
    for (int m = 0; m < M_; m++)
        v[1 + m] = ((const float4*)(masked + ((size_t)m * B_ + i) * D_))[t];

    float vals[9];
    #pragma unroll
    for (int r = 0; r < 5; r++)
        vals[r] = v[r].x * v[r].x + v[r].y * v[r].y + v[r].z * v[r].z + v[r].w * v[r].w;
    #pragma unroll
    for (int m = 0; m < M_; m++)
        vals[5 + m] = v[0].x * v[1 + m].x + v[0].y * v[1 + m].y
                    + v[0].z * v[1 + m].z + v[0].w * v[1 + m].w;

    __shared__ float sm[2][9][4];
    #pragma unroll
    for (int q = 0; q < 9; q++) {
        float s = vals[q];
        #pragma unroll
        for (int off = 16; off > 0; off >>= 1)
            s += __shfl_down_sync(0xffffffffu, s, off);
        if ((t & 31) == 0) sm[half][q][t >> 5] = s;
    }
    __syncthreads();
    __shared__ float s_inv[2][5];
    if (t < 5) {
        float tot = sm[half][t][0] + sm[half][t][1] + sm[half][t][2] + sm[half][t][3];
        s_inv[half][t] = 16.0f / fmaxf(sqrtf(tot), 1e-12f);   // x16 for e4m3
    }
    if (t == 0) {
        const float invT = 1.0f / get_temp(d_iter[0]);
        float no = fmaxf(sqrtf(sm[half][0][0] + sm[half][0][1] + sm[half][0][2] + sm[half][0][3]), 1e-12f);
        float pos = 0.0f;
        #pragma unroll
        for (int m = 0; m < M_; m++) {
            float nk = fmaxf(sqrtf(sm[half][1 + m][0] + sm[half][1 + m][1]
                                 + sm[half][1 + m][2] + sm[half][1 + m][3]), 1e-12f);
            float d  = sm[half][5 + m][0] + sm[half][5 + m][1]
                     + sm[half][5 + m][2] + sm[half][5 + m][3];
            pos += __expf(d / (no * nk) * invT);
        }
        g_pos[i] = pos;
        g_denom[i] = 0.0f;
        if (i == 0) { g_tile_ctr = 0; g_done_ctr = 0; }
    }
    __syncthreads();
    #pragma unroll
    for (int r = 0; r < 5; r++) {
        const float inv = s_inv[half][r];
        uint16_t lo = pack_e4m3x2(v[r].x * inv, v[r].y * inv);
        uint16_t hi = pack_e4m3x2(v[r].z * inv, v[r].w * inv);
        const int row = r == 0 ? i : (r * B_ + i);
        ((uint32_t*)(g_fp8 + (size_t)row * D_))[t] = (uint32_t)lo | ((uint32_t)hi << 16);
    }
}

// ---------------------------------------------------------------------------
// Kernel 2: persistent FP8 (f16-acc) exp-GEMM, work-stealing over 4624 tiles,
// with fused loss+finalize done by the last CTA to finish.
// grid = 444 CTAs (148 SM x 3). Denoms scaled by 2^-8.
// ---------------------------------------------------------------------------
#define TILE 128
#define NCHUNK 4
#define NSTAGE 2
#define STG_A_SZ (TILE * 128)   // 16 KB
#define STG_B_SZ (TILE * 128)   // 16 KB
#define SMEM_A_OFF 1024
#define SMEM_B_OFF (SMEM_A_OFF + NSTAGE * STG_A_SZ)
#define SMEM_TOTAL (SMEM_B_OFF + NSTAGE * STG_B_SZ)   // 66560 B
#define NTILE_TOTAL (32 + 496 + 4096)                  // 4624
#define GRID_GEMM (148 * 3)

__device__ __forceinline__ void load_chunk(int chunk, int stage, uint32_t sb,
                                           const char* gA, const char* gB, int tid) {
    const int row = tid >> 1;
    const int c0 = (tid & 1) * 4;
    const char* asrc = gA + (size_t)row * D_ + chunk * 128 + c0 * 16;
    const char* bsrc = gB + (size_t)row * D_ + chunk * 128 + c0 * 16;
    const uint32_t abase = sb + SMEM_A_OFF + stage * STG_A_SZ;
    const uint32_t bbase = sb + SMEM_B_OFF + stage * STG_B_SZ;
    #pragma unroll
    for (int c = 0; c < 4; c++) {
        uint32_t off = (uint32_t)row * 128 + (c0 + c) * 16;
        CP_ASYNC16(abase + swz128(off), asrc + c * 16);
        CP_ASYNC16(bbase + swz128(off), bsrc + c * 16);
    }
}

__global__ __launch_bounds__(256, 3) void gemm_fp8_kernel(const int* __restrict__ d_iter,
                                                          float* __restrict__ out) {
    extern __shared__ __align__(1024) char smem[];
    float* sdenom_row = (float*)smem;          // 128 floats [0,512)
    float* sdenom_col = (float*)(smem + 512);  // 128 floats [512,1024)
    uint32_t sb = smem_u32(smem);
    __shared__ int s_tile;

    const int tid  = threadIdx.x;
    const int lane = tid & 31;
    const int wid  = tid >> 5;
    const int warpM = wid & 1;
    const int warpN = wid >> 1;

    const float invT = 1.0f / get_temp(d_iter[0]);

    for (;;) {
        if (tid == 0) s_tile = atomicAdd(&g_tile_ctr, 1);
        __syncthreads();
        const int bid = s_tile;
        if (bid >= NTILE_TOTAL) break;

        // --- tile mapping ---
        int tr, tc;
        bool sym = false, diag = false;
        if (bid < 32) {                 // diagonal orig-orig tiles
            tr = bid; tc = bid; diag = true;
        } else if (bid < 528) {         // upper-triangle orig-orig (r < c)
            int k = bid - 32;
            int r = 0;
            while (k >= 31 - r) { k -= 31 - r; r++; }
            tr = r; tc = r + 1 + k;
            sym = true;
        } else {                        // orig x masked tiles
            int k = bid - 528;
            tr = k >> 7;
            tc = 32 + (k & 127);
        }
        const int rowBase = tr * TILE;
        const int colBase = tc * TILE;
        const char* gA = (const char*)(g_fp8 + (size_t)rowBase * D_);
        const char* gB = (const char*)(g_fp8 + (size_t)colBase * D_);

        if (tid < TILE) { sdenom_row[tid] = 0.0f; sdenom_col[tid] = 0.0f; }

        load_chunk(0, 0, sb, gA, gB, tid); CP_COMMIT();

        uint32_t acc[4][4][2];
        #pragma unroll
        for (int mt = 0; mt < 4; mt++)
            #pragma unroll
            for (int nt = 0; nt < 4; nt++) { acc[mt][nt][0] = 0u; acc[mt][nt][1] = 0u; }

        const int a_row = warpM * 64 + (lane & 15);
        const int a_kb  = (lane >> 4) * 16;
        const int b_row = warpN * 32 + ((lane >> 4) << 3) + (lane & 7);
        const int b_kb  = ((lane >> 3) & 1) * 16;

        #pragma unroll
        for (int k = 0; k < NCHUNK; k++) {
            asm volatile("cp.async.wait_group 0;" ::: "memory");
            __syncthreads();
            if (k + 1 < NCHUNK) {
                load_chunk(k + 1, (k + 1) & 1, sb, gA, gB, tid);
                CP_COMMIT();
            }
            const int st = k & 1;
            const uint32_t Ab = sb + SMEM_A_OFF + st * STG_A_SZ;
            const uint32_t Bb = sb + SMEM_B_OFF + st * STG_B_SZ;

            #pragma unroll
            for (int kk = 0; kk < 4; kk++) {
                uint32_t a[4][4];
                #pragma unroll
                for (int mt = 0; mt < 4; mt++) {
                    uint32_t off = (uint32_t)(a_row + mt * 16) * 128 + kk * 32 + a_kb;
                    LDMATRIX_X4(a[mt][0], a[mt][1], a[mt][2], a[mt][3], Ab + swz128(off));
                }
                uint32_t b[2][4];
                #pragma unroll
                for (int ntp = 0; ntp < 2; ntp++) {
                    uint32_t off = (uint32_t)(b_row + ntp * 16) * 128 + kk * 32 + b_kb;
                    LDMATRIX_X4(b[ntp][0], b[ntp][1], b[ntp][2], b[ntp][3], Bb + swz128(off));
                }
                #pragma unroll
                for (int mt = 0; mt < 4; mt++)
                    #pragma unroll
                    for (int nt = 0; nt < 4; nt++)
                        MMA_FP8_H(acc[mt][nt], a[mt], b[nt >> 1][(nt & 1) * 2],
                                  b[nt >> 1][(nt & 1) * 2 + 1]);
            }
        }

        // Epilogue. acc = 256*sim.
        if (!diag) {
            const __half2 kh = __float2half2_rn(invT * 1.44269504089f * (1.0f / 256.0f));
            const __half2 ch = __float2half2_rn(-8.0f);
            const __half2 zh = __float2half2_rn(0.0f);
            __half2 cs[4] = {zh, zh, zh, zh};
            #pragma unroll
            for (int mt = 0; mt < 4; mt++) {
                __half2 s0 = zh, s1 = zh;
                #pragma unroll
                for (int nt = 0; nt < 4; nt++) {
                    __half2 y0 = __hfma2(*(__half2*)&acc[mt][nt][0], kh, ch);
                    __half2 y1 = __hfma2(*(__half2*)&acc[mt][nt][1], kh, ch);
                    __half2 e0, e1;
                    *(uint32_t*)&e0 = ex2_f16x2(*(uint32_t*)&y0);
                    *(uint32_t*)&e1 = ex2_f16x2(*(uint32_t*)&y1);
                    s0 = __hadd2(s0, e0);
                    s1 = __hadd2(s1, e1);
                    if (sym) cs[nt] = __hadd2(cs[nt], __hadd2(e0, e1));
                }
                float2 f0 = __half22float2(s0);
                float2 f1 = __half22float2(s1);
                float rs0 = f0.x + f0.y;
                float rs1 = f1.x + f1.y;
                rs0 += __shfl_xor_sync(0xffffffffu, rs0, 1);
                rs0 += __shfl_xor_sync(0xffffffffu, rs0, 2);
                rs1 += __shfl_xor_sync(0xffffffffu, rs1, 1);
                rs1 += __shfl_xor_sync(0xffffffffu, rs1, 2);
                const int r0 = warpM * 64 + mt * 16 + (lane >> 2);
                if ((lane & 3) == 0) {
                    atomicAdd(&sdenom_row[r0], rs0);
                    atomicAdd(&sdenom_row[r0 + 8], rs1);
                }
            }
            if (sym) {
                #pragma unroll
                for (int nt = 0; nt < 4; nt++) {
                    uint32_t h = *(uint32_t*)&cs[nt];
                    #pragma unroll
                    for (int off = 4; off <= 16; off <<= 1) {
                        uint32_t o = __shfl_xor_sync(0xffffffffu, h, off);
                        __half2 sum = __hadd2(*(__half2*)&h, *(__half2*)&o);
                        h = *(uint32_t*)&sum;
                    }
                    if (lane < 4) {
                        float2 f = __half22float2(*(__half2*)&h);
                        const int c = warpN * 32 + nt * 8 + 2 * lane;
                        atomicAdd(&sdenom_col[c], f.x);
                        atomicAdd(&sdenom_col[c + 1], f.y);
                    }
                }
            }
        } else {
            const float sc = invT * (1.0f / 256.0f);
            const float bias = -8.0f * 0.69314718056f;
            #pragma unroll
            for (int mt = 0; mt < 4; mt++) {
                const int r0 = warpM * 64 + mt * 16 + (lane >> 2);
                const int gi0 = rowBase + r0;
                const int gi1 = gi0 + 8;
                float rs0 = 0.0f, rs1 = 0.0f;
                #pragma unroll
                for (int nt = 0; nt < 4; nt++) {
                    const int col = colBase + warpN * 32 + nt * 8 + 2 * (lane & 3);
                    float2 f01 = __half22float2(*(const __half2*)&acc[mt][nt][0]);
                    float2 f23 = __half22float2(*(const __half2*)&acc[mt][nt][1]);
                    float e0 = __expf(f01.x * sc + bias);
                    float e1 = __expf(f01.y * sc + bias);
                    float e2 = __expf(f23.x * sc + bias);
                    float e3 = __expf(f23.y * sc + bias);
                    if (col != gi0)     rs0 += e0;
                    if (col + 1 != gi0) rs0 += e1;
                    if (col != gi1)     rs1 += e2;
                    if (col + 1 != gi1) rs1 += e3;
                }
                rs0 += __shfl_xor_sync(0xffffffffu, rs0, 1);
                rs0 += __shfl_xor_sync(0xffffffffu, rs0, 2);
                rs1 += __shfl_xor_sync(0xffffffffu, rs1, 1);
                rs1 += __shfl_xor_sync(0xffffffffu, rs1, 2);
                if ((lane & 3) == 0) {
                    atomicAdd(&sdenom_row[r0], rs0);
                    atomicAdd(&sdenom_row[r0 + 8], rs1);
                }
            }
        }

        __syncthreads();
        if (tid < TILE) {
            atomicAdd(&g_denom[rowBase + tid], sdenom_row[tid]);
            if (sym) atomicAdd(&g_denom[colBase + tid], sdenom_col[tid]);
        }
        __syncthreads();   // smem accumulators reused next tile
    }

    // ---- fused loss + finalize: last CTA to finish does the reduction ----
    __syncthreads();
    __shared__ int s_rank;
    if (tid == 0) {
        __threadfence();   // make this CTA's denom atomics globally visible
        s_rank = atomicAdd(&g_done_ctr, 1);
    }
    __syncthreads();
    if (s_rank == GRID_GEMM - 1) {
        __threadfence();   // see all other CTAs' writes
        float loss = 0.0f;
        for (int i = tid; i < B_; i += 256)
            loss += logf(g_denom[i] * 256.0f + 1e-8f) - logf(g_pos[i]);
        #pragma unroll
        for (int off = 16; off > 0; off >>= 1)
            loss += __shfl_down_sync(0xffffffffu, loss, off);
        float* sred = sdenom_row;   // reuse smem
        if ((tid & 31) == 0) sred[tid >> 5] = loss;
        __syncthreads();
        if (tid == 0) {
            float v = 0.0f;
            #pragma unroll
            for (int w = 0; w < 8; w++) v += sred[w];
            out[0] = v * (1.0f / (float)B_);
        }
    }
}

// ---------------------------------------------------------------------------
extern "C" void kernel_launch(void* const* d_in, const int* in_sizes, int n_in,
                              void* d_out, int out_size) {
    const float* orig   = (const float*)d_in[0];
    const float* masked = (const float*)d_in[1];
    const int*   iter   = (const int*)d_in[2];
    float* out = (float*)d_out;

    cudaFuncSetAttribute(gemm_fp8_kernel,
                         cudaFuncAttributeMaxDynamicSharedMemorySize, SMEM_TOTAL);

    prep_kernel<<<B_ / 2, 256>>>(orig, masked, iter);
    gemm_fp8_kernel<<<GRID_GEMM, 256, SMEM_TOTAL>>>(iter, out);
}

// round 16
// speedup vs baseline: 1.0211x; 1.0211x over previous
#include <cuda_runtime.h>
#include <cuda_bf16.h>
#include <cuda_fp16.h>
#include <math.h>
#include <stdint.h>

#define B_ 4096
#define M_ 4
#define D_ 512
#define N_ ((M_ + 1) * B_)   // 20480

// Static device scratch (no runtime allocation)
__device__ uint8_t g_fp8[(size_t)N_ * D_];   // normalized rows * 16, e4m3, 10 MB
__device__ float g_denom[B_];                // stores denom * 2^-8
__device__ float g_pos[B_];
__device__ int   g_tile_ctr;

__device__ __forceinline__ float get_temp(int it) {
    if (it >= 300000) return 0.05f;
    float progress = (float)it / 300000.0f;
    return 0.05f + 0.5f * (0.2f - 0.05f) * (1.0f + cosf(3.14159265358979323846f * progress));
}

__device__ __forceinline__ uint32_t smem_u32(const void* p) {
    uint32_t a;
    asm("{ .reg .u64 t; cvta.to.shared.u64 t, %1; cvt.u32.u64 %0, t; }" : "=r"(a) : "l"(p));
    return a;
}

__device__ __forceinline__ uint32_t swz128(uint32_t off) {
    return off ^ ((off >> 3) & 0x70);
}

#define CP_ASYNC16(dst, src) \
    asm volatile("cp.async.cg.shared.global [%0], [%1], 16;" :: "r"(dst), "l"(src) : "memory")
#define CP_COMMIT() asm volatile("cp.async.commit_group;" ::: "memory")

#define LDMATRIX_X4(r0, r1, r2, r3, addr) \
    asm volatile("ldmatrix.sync.aligned.m8n8.x4.shared.b16 {%0,%1,%2,%3}, [%4];" \
                 : "=r"(r0), "=r"(r1), "=r"(r2), "=r"(r3) : "r"(addr))

// FP8 e4m3 inputs, F16 accumulators (2 regs = 4 packed halves)
#define MMA_FP8_H(d, a, b0, b1) \
    asm volatile("mma.sync.aligned.m16n8k32.row.col.f16.e4m3.e4m3.f16 " \
                 "{%0,%1}, {%2,%3,%4,%5}, {%6,%7}, {%0,%1};" \
                 : "+r"((d)[0]), "+r"((d)[1]) \
                 : "r"((a)[0]), "r"((a)[1]), "r"((a)[2]), "r"((a)[3]), \
                   "r"(b0), "r"(b1))

__device__ __forceinline__ uint32_t ex2_f16x2(uint32_t y) {
    uint32_t r;
    asm("ex2.approx.f16x2 %0, %1;" : "=r"(r) : "r"(y));
    return r;
}

__device__ __forceinline__ uint16_t pack_e4m3x2(float lo, float hi) {
    uint16_t r;
    asm("cvt.rn.satfinite.e4m3x2.f32 %0, %1, %2;" : "=h"(r) : "f"(hi), "f"(lo));
    return r;
}

// ---------------------------------------------------------------------------
// Kernel 1 (fused prep): 2048 blocks x 256 threads; each half-block (128 thr)
// handles one orig row: norms, exact positives, quantize 5 rows to fp8.
// 2 rows per CTA doubles loads in flight (prep was issue/latency-bound).
// ---------------------------------------------------------------------------
__global__ __launch_bounds__(256) void prep_kernel(const float* __restrict__ orig,
                                                   const float* __restrict__ masked,
                                                   const int* __restrict__ d_iter) {
    const int half = threadIdx.x >> 7;            // 0/1
    const int i = blockIdx.x * 2 + half;          // orig row
    const int t = threadIdx.x & 127;              // 0..127 within half
    float4 v[5];
    v[0] = ((const float4*)(orig + (size_t)i * D_))[t];
    #pragma unroll
    for (int m = 0; m < M_; m++)
        v[1 + m] = ((const float4*)(masked + ((size_t)m * B_ + i) * D_))[t];

    float vals[9];
    #pragma unroll
    for (int r = 0; r < 5; r++)
        vals[r] = v[r].x * v[r].x + v[r].y * v[r].y + v[r].z * v[r].z + v[r].w * v[r].w;
    #pragma unroll
    for (int m = 0; m < M_; m++)
        vals[5 + m] = v[0].x * v[1 + m].x + v[0].y * v[1 + m].y
                    + v[0].z * v[1 + m].z + v[0].w * v[1 + m].w;

    __shared__ float sm[2][9][4];
    #pragma unroll
    for (int q = 0; q < 9; q++) {
        float s = vals[q];
        #pragma unroll
        for (int off = 16; off > 0; off >>= 1)
            s += __shfl_down_sync(0xffffffffu, s, off);
        if ((t & 31) == 0) sm[half][q][t >> 5] = s;
    }
    __syncthreads();
    __shared__ float s_inv[2][5];
    if (t < 5) {
        float tot = sm[half][t][0] + sm[half][t][1] + sm[half][t][2] + sm[half][t][3];
        s_inv[half][t] = 16.0f / fmaxf(sqrtf(tot), 1e-12f);   // x16 for e4m3
    }
    if (t == 0) {
        const float invT = 1.0f / get_temp(d_iter[0]);
        float no = fmaxf(sqrtf(sm[half][0][0] + sm[half][0][1]
                             + sm[half][0][2] + sm[half][0][3]), 1e-12f);
        float pos = 0.0f;
        #pragma unroll
        for (int m = 0; m < M_; m++) {
            float nk = fmaxf(sqrtf(sm[half][1 + m][0] + sm[half][1 + m][1]
                                 + sm[half][1 + m][2] + sm[half][1 + m][3]), 1e-12f);
            float d  = sm[half][5 + m][0] + sm[half][5 + m][1]
                     + sm[half][5 + m][2] + sm[half][5 + m][3];
            pos += __expf(d / (no * nk) * invT);
        }
        g_pos[i] = pos;
        g_denom[i] = 0.0f;
        if (i == 0) g_tile_ctr = 0;
    }
    __syncthreads();
    #pragma unroll
    for (int r = 0; r < 5; r++) {
        const float inv = s_inv[half][r];
        uint16_t lo = pack_e4m3x2(v[r].x * inv, v[r].y * inv);
        uint16_t hi = pack_e4m3x2(v[r].z * inv, v[r].w * inv);
        const int row = r == 0 ? i : (r * B_ + i);
        ((uint32_t*)(g_fp8 + (size_t)row * D_))[t] = (uint32_t)lo | ((uint32_t)hi << 16);
    }
}

// ---------------------------------------------------------------------------
// Kernel 2: persistent FP8 (f16-acc) exp-GEMM, work-stealing over 4624 tiles.
// grid = 444 CTAs (148 SM x 3). Tile list: 32 diag + 496 upper-tri (sym,
// row+col scatter) + 4096 orig x masked. Denoms scaled by 2^-8.
// (R14's proven kernel, unchanged.)
// ---------------------------------------------------------------------------
#define TILE 128
#define NCHUNK 4
#define NSTAGE 2
#define STG_A_SZ (TILE * 128)   // 16 KB
#define STG_B_SZ (TILE * 128)   // 16 KB
#define SMEM_A_OFF 1024
#define SMEM_B_OFF (SMEM_A_OFF + NSTAGE * STG_A_SZ)
#define SMEM_TOTAL (SMEM_B_OFF + NSTAGE * STG_B_SZ)   // 66560 B
#define NTILE_TOTAL (32 + 496 + 4096)                  // 4624
#define GRID_GEMM (148 * 3)

__device__ __forceinline__ void load_chunk(int chunk, int stage, uint32_t sb,
                                           const char* gA, const char* gB, int tid) {
    const int row = tid >> 1;
    const int c0 = (tid & 1) * 4;
    const char* asrc = gA + (size_t)row * D_ + chunk * 128 + c0 * 16;
    const char* bsrc = gB + (size_t)row * D_ + chunk * 128 + c0 * 16;
    const uint32_t abase = sb + SMEM_A_OFF + stage * STG_A_SZ;
    const uint32_t bbase = sb + SMEM_B_OFF + stage * STG_B_SZ;
    #pragma unroll
    for (int c = 0; c < 4; c++) {
        uint32_t off = (uint32_t)row * 128 + (c0 + c) * 16;
        CP_ASYNC16(abase + swz128(off), asrc + c * 16);
        CP_ASYNC16(bbase + swz128(off), bsrc + c * 16);
    }
}

__global__ __launch_bounds__(256, 3) void gemm_fp8_kernel(const int* __restrict__ d_iter) {
    extern __shared__ __align__(1024) char smem[];
    float* sdenom_row = (float*)smem;          // 128 floats [0,512)
    float* sdenom_col = (float*)(smem + 512);  // 128 floats [512,1024)
    uint32_t sb = smem_u32(smem);
    __shared__ int s_tile;

    const int tid  = threadIdx.x;
    const int lane = tid & 31;
    const int wid  = tid >> 5;
    const int warpM = wid & 1;
    const int warpN = wid >> 1;

    const float invT = 1.0f / get_temp(d_iter[0]);

    for (;;) {
        if (tid == 0) s_tile = atomicAdd(&g_tile_ctr, 1);
        __syncthreads();
        const int bid = s_tile;
        if (bid >= NTILE_TOTAL) break;

        // --- tile mapping ---
        int tr, tc;
        bool sym = false, diag = false;
        if (bid < 32) {                 // diagonal orig-orig tiles
            tr = bid; tc = bid; diag = true;
        } else if (bid < 528) {         // upper-triangle orig-orig (r < c)
            int k = bid - 32;
            int r = 0;
            while (k >= 31 - r) { k -= 31 - r; r++; }
            tr = r; tc = r + 1 + k;
            sym = true;
        } else {                        // orig x masked tiles
            int k = bid - 528;
            tr = k >> 7;
            tc = 32 + (k & 127);
        }
        const int rowBase = tr * TILE;
        const int colBase = tc * TILE;
        const char* gA = (const char*)(g_fp8 + (size_t)rowBase * D_);
        const char* gB = (const char*)(g_fp8 + (size_t)colBase * D_);

        if (tid < TILE) { sdenom_row[tid] = 0.0f; sdenom_col[tid] = 0.0f; }

        load_chunk(0, 0, sb, gA, gB, tid); CP_COMMIT();

        uint32_t acc[4][4][2];
        #pragma unroll
        for (int mt = 0; mt < 4; mt++)
            #pragma unroll
            for (int nt = 0; nt < 4; nt++) { acc[mt][nt][0] = 0u; acc[mt][nt][1] = 0u; }

        const int a_row = warpM * 64 + (lane & 15);
        const int a_kb  = (lane >> 4) * 16;
        const int b_row = warpN * 32 + ((lane >> 4) << 3) + (lane & 7);
        const int b_kb  = ((lane >> 3) & 1) * 16;

        #pragma unroll
        for (int k = 0; k < NCHUNK; k++) {
            asm volatile("cp.async.wait_group 0;" ::: "memory");
            __syncthreads();
            if (k + 1 < NCHUNK) {
                load_chunk(k + 1, (k + 1) & 1, sb, gA, gB, tid);
                CP_COMMIT();
            }
            const int st = k & 1;
            const uint32_t Ab = sb + SMEM_A_OFF + st * STG_A_SZ;
            const uint32_t Bb = sb + SMEM_B_OFF + st * STG_B_SZ;

            #pragma unroll
            for (int kk = 0; kk < 4; kk++) {
                uint32_t a[4][4];
                #pragma unroll
                for (int mt = 0; mt < 4; mt++) {
                    uint32_t off = (uint32_t)(a_row + mt * 16) * 128 + kk * 32 + a_kb;
                    LDMATRIX_X4(a[mt][0], a[mt][1], a[mt][2], a[mt][3], Ab + swz128(off));
                }
                uint32_t b[2][4];
                #pragma unroll
                for (int ntp = 0; ntp < 2; ntp++) {
                    uint32_t off = (uint32_t)(b_row + ntp * 16) * 128 + kk * 32 + b_kb;
                    LDMATRIX_X4(b[ntp][0], b[ntp][1], b[ntp][2], b[ntp][3], Bb + swz128(off));
                }
                #pragma unroll
                for (int mt = 0; mt < 4; mt++)
                    #pragma unroll
                    for (int nt = 0; nt < 4; nt++)
                        MMA_FP8_H(acc[mt][nt], a[mt], b[nt >> 1][(nt & 1) * 2],
                                  b[nt >> 1][(nt & 1) * 2 + 1]);
            }
        }

        // Epilogue. acc = 256*sim.
        if (!diag) {
            const __half2 kh = __float2half2_rn(invT * 1.44269504089f * (1.0f / 256.0f));
            const __half2 ch = __float2half2_rn(-8.0f);
            const __half2 zh = __float2half2_rn(0.0f);
            __half2 cs[4] = {zh, zh, zh, zh};
            #pragma unroll
            for (int mt = 0; mt < 4; mt++) {
                __half2 s0 = zh, s1 = zh;
                #pragma unroll
                for (int nt = 0; nt < 4; nt++) {
                    __half2 y0 = __hfma2(*(__half2*)&acc[mt][nt][0], kh, ch);
                    __half2 y1 = __hfma2(*(__half2*)&acc[mt][nt][1], kh, ch);
                    __half2 e0, e1;
                    *(uint32_t*)&e0 = ex2_f16x2(*(uint32_t*)&y0);
                    *(uint32_t*)&e1 = ex2_f16x2(*(uint32_t*)&y1);
                    s0 = __hadd2(s0, e0);
                    s1 = __hadd2(s1, e1);
                    if (sym) cs[nt] = __hadd2(cs[nt], __hadd2(e0, e1));
                }
                float2 f0 = __half22float2(s0);
                float2 f1 = __half22float2(s1);
                float rs0 = f0.x + f0.y;
                float rs1 = f1.x + f1.y;
                rs0 += __shfl_xor_sync(0xffffffffu, rs0, 1);
                rs0 += __shfl_xor_sync(0xffffffffu, rs0, 2);
                rs1 += __shfl_xor_sync(0xffffffffu, rs1, 1);
                rs1 += __shfl_xor_sync(0xffffffffu, rs1, 2);
                const int r0 = warpM * 64 + mt * 16 + (lane >> 2);
                if ((lane & 3) == 0) {
                    atomicAdd(&sdenom_row[r0], rs0);
                    atomicAdd(&sdenom_row[r0 + 8], rs1);
                }
            }
            if (sym) {
                #pragma unroll
                for (int nt = 0; nt < 4; nt++) {
                    uint32_t h = *(uint32_t*)&cs[nt];
                    #pragma unroll
                    for (int off = 4; off <= 16; off <<= 1) {
                        uint32_t o = __shfl_xor_sync(0xffffffffu, h, off);
                        __half2 sum = __hadd2(*(__half2*)&h, *(__half2*)&o);
                        h = *(uint32_t*)&sum;
                    }
                    if (lane < 4) {
                        float2 f = __half22float2(*(__half2*)&h);
                        const int c = warpN * 32 + nt * 8 + 2 * lane;
                        atomicAdd(&sdenom_col[c], f.x);
                        atomicAdd(&sdenom_col[c + 1], f.y);
                    }
                }
            }
        } else {
            const float sc = invT * (1.0f / 256.0f);
            const float bias = -8.0f * 0.69314718056f;
            #pragma unroll
            for (int mt = 0; mt < 4; mt++) {
                const int r0 = warpM * 64 + mt * 16 + (lane >> 2);
                const int gi0 = rowBase + r0;
                const int gi1 = gi0 + 8;
                float rs0 = 0.0f, rs1 = 0.0f;
                #pragma unroll
                for (int nt = 0; nt < 4; nt++) {
                    const int col = colBase + warpN * 32 + nt * 8 + 2 * (lane & 3);
                    float2 f01 = __half22float2(*(const __half2*)&acc[mt][nt][0]);
                    float2 f23 = __half22float2(*(const __half2*)&acc[mt][nt][1]);
                    float e0 = __expf(f01.x * sc + bias);
                    float e1 = __expf(f01.y * sc + bias);
                    float e2 = __expf(f23.x * sc + bias);
                    float e3 = __expf(f23.y * sc + bias);
                    if (col != gi0)     rs0 += e0;
                    if (col + 1 != gi0) rs0 += e1;
                    if (col != gi1)     rs1 += e2;
                    if (col + 1 != gi1) rs1 += e3;
                }
                rs0 += __shfl_xor_sync(0xffffffffu, rs0, 1);
                rs0 += __shfl_xor_sync(0xffffffffu, rs0, 2);
                rs1 += __shfl_xor_sync(0xffffffffu, rs1, 1);
                rs1 += __shfl_xor_sync(0xffffffffu, rs1, 2);
                if ((lane & 3) == 0) {
                    atomicAdd(&sdenom_row[r0], rs0);
                    atomicAdd(&sdenom_row[r0 + 8], rs1);
                }
            }
        }

        __syncthreads();
        if (tid < TILE) {
            atomicAdd(&g_denom[rowBase + tid], sdenom_row[tid]);
            if (sym) atomicAdd(&g_denom[colBase + tid], sdenom_col[tid]);
        }
        __syncthreads();   // smem accumulators reused next tile
    }
}

// ---------------------------------------------------------------------------
// Kernel 3 (fused loss+finalize): one block, 1024 threads, 4 rows each.
// g_denom holds denom * 2^-8.
// ---------------------------------------------------------------------------
__global__ __launch_bounds__(1024) void loss_finalize_kernel(float* __restrict__ out) {
    const int t = threadIdx.x;
    float loss = 0.0f;
    #pragma unroll
    for (int q = 0; q < 4; q++) {
        const int i = t + q * 1024;
        loss += logf(g_denom[i] * 256.0f + 1e-8f) - logf(g_pos[i]);
    }
    #pragma unroll
    for (int off = 16; off > 0; off >>= 1)
        loss += __shfl_down_sync(0xffffffffu, loss, off);
    __shared__ float sm[32];
    if ((t & 31) == 0) sm[t >> 5] = loss;
    __syncthreads();
    if (t < 32) {
        float v = sm[t];
        #pragma unroll
        for (int off = 16; off > 0; off >>= 1)
            v += __shfl_down_sync(0xffffffffu, v, off);
        if (t == 0) out[0] = v * (1.0f / (float)B_);
    }
}

// ---------------------------------------------------------------------------
extern "C" void kernel_launch(void* const* d_in, const int* in_sizes, int n_in,
                              void* d_out, int out_size) {
    const float* orig   = (const float*)d_in[0];
    const float* masked = (const float*)d_in[1];
    const int*   iter   = (const int*)d_in[2];
    float* out = (float*)d_out;

    cudaFuncSetAttribute(gemm_fp8_kernel,
                         cudaFuncAttributeMaxDynamicSharedMemorySize, SMEM_TOTAL);

    prep_kernel<<<B_ / 2, 256>>>(orig, masked, iter);
    gemm_fp8_kernel<<<GRID_GEMM, 256, SMEM_TOTAL>>>(iter);
    loss_finalize_kernel<<<1, 1024>>>(out);
}

// round 17
// speedup vs baseline: 1.0262x; 1.0050x over previous
#include <cuda_runtime.h>
#include <cuda_bf16.h>
#include <cuda_fp16.h>
#include <math.h>
#include <stdint.h>

#define B_ 4096
#define M_ 4
#define D_ 512
#define N_ ((M_ + 1) * B_)   // 20480

// Static device scratch (no runtime allocation)
__device__ uint8_t g_fp8[(size_t)N_ * D_];   // normalized rows * 16, e4m3, 10 MB
__device__ float g_denom[B_];                // stores denom * 2^-8
__device__ float g_pos[B_];
__device__ int   g_tile_ctr;

__device__ __forceinline__ float get_temp(int it) {
    if (it >= 300000) return 0.05f;
    float progress = (float)it / 300000.0f;
    return 0.05f + 0.5f * (0.2f - 0.05f) * (1.0f + cosf(3.14159265358979323846f * progress));
}

__device__ __forceinline__ uint32_t smem_u32(const void* p) {
    uint32_t a;
    asm("{ .reg .u64 t; cvta.to.shared.u64 t, %1; cvt.u32.u64 %0, t; }" : "=r"(a) : "l"(p));
    return a;
}

__device__ __forceinline__ uint32_t swz128(uint32_t off) {
    return off ^ ((off >> 3) & 0x70);
}

#define CP_ASYNC16(dst, src) \
    asm volatile("cp.async.cg.shared.global [%0], [%1], 16;" :: "r"(dst), "l"(src) : "memory")
#define CP_COMMIT() asm volatile("cp.async.commit_group;" ::: "memory")

#define LDMATRIX_X4(r0, r1, r2, r3, addr) \
    asm volatile("ldmatrix.sync.aligned.m8n8.x4.shared.b16 {%0,%1,%2,%3}, [%4];" \
                 : "=r"(r0), "=r"(r1), "=r"(r2), "=r"(r3) : "r"(addr))

// FP8 e4m3 inputs, F16 accumulators (2 regs = 4 packed halves)
#define MMA_FP8_H(d, a, b0, b1) \
    asm volatile("mma.sync.aligned.m16n8k32.row.col.f16.e4m3.e4m3.f16 " \
                 "{%0,%1}, {%2,%3,%4,%5}, {%6,%7}, {%0,%1};" \
                 : "+r"((d)[0]), "+r"((d)[1]) \
                 : "r"((a)[0]), "r"((a)[1]), "r"((a)[2]), "r"((a)[3]), \
                   "r"(b0), "r"(b1))

__device__ __forceinline__ uint32_t ex2_f16x2(uint32_t y) {
    uint32_t r;
    asm("ex2.approx.f16x2 %0, %1;" : "=r"(r) : "r"(y));
    return r;
}

__device__ __forceinline__ uint16_t pack_e4m3x2(float lo, float hi) {
    uint16_t r;
    asm("cvt.rn.satfinite.e4m3x2.f32 %0, %1, %2;" : "=h"(r) : "f"(hi), "f"(lo));
    return r;
}

// ---------------------------------------------------------------------------
// Kernel 1 (warp-autonomous prep): one warp per orig row (8 rows/CTA).
// Each thread preloads 20 float4 (MLP 20); 9 butterfly warp reductions
// (no smem, no __syncthreads); all lanes compute scales; quantize to fp8.
// ---------------------------------------------------------------------------
__global__ __launch_bounds__(256) void prep_kernel(const float* __restrict__ orig,
                                                   const float* __restrict__ masked,
                                                   const int* __restrict__ d_iter) {
    const int w = threadIdx.x >> 5;               // warp 0..7
    const int lane = threadIdx.x & 31;
    const int i = blockIdx.x * 8 + w;             // orig row

    // Preload all 5 rows: thread lane holds float4 indices lane+32c, c=0..3
    float4 v[5][4];
    {
        const float4* p0 = (const float4*)(orig + (size_t)i * D_);
        #pragma unroll
        for (int c = 0; c < 4; c++) v[0][c] = p0[lane + 32 * c];
        #pragma unroll
        for (int m = 0; m < M_; m++) {
            const float4* pm = (const float4*)(masked + ((size_t)m * B_ + i) * D_);
            #pragma unroll
            for (int c = 0; c < 4; c++) v[1 + m][c] = pm[lane + 32 * c];
        }
    }

    // 9 per-thread partials: 5 self-dots + 4 cross-dots
    float vals[9];
    #pragma unroll
    for (int r = 0; r < 5; r++) {
        float s = 0.0f;
        #pragma unroll
        for (int c = 0; c < 4; c++)
            s += v[r][c].x * v[r][c].x + v[r][c].y * v[r][c].y
               + v[r][c].z * v[r][c].z + v[r][c].w * v[r][c].w;
        vals[r] = s;
    }
    #pragma unroll
    for (int m = 0; m < M_; m++) {
        float s = 0.0f;
        #pragma unroll
        for (int c = 0; c < 4; c++)
            s += v[0][c].x * v[1 + m][c].x + v[0][c].y * v[1 + m][c].y
               + v[0][c].z * v[1 + m][c].z + v[0][c].w * v[1 + m][c].w;
        vals[5 + m] = s;
    }

    // Butterfly reduce: every lane ends with the 9 totals
    #pragma unroll
    for (int off = 16; off > 0; off >>= 1)
        #pragma unroll
        for (int q = 0; q < 9; q++)
            vals[q] += __shfl_xor_sync(0xffffffffu, vals[q], off);

    // Per-lane scales (redundant but sync-free)
    float inv[5];
    #pragma unroll
    for (int r = 0; r < 5; r++)
        inv[r] = 16.0f / fmaxf(sqrtf(vals[r]), 1e-12f);   // x16 for e4m3 range

    if (lane == 0) {
        const float invT = 1.0f / get_temp(d_iter[0]);
        const float no = fmaxf(sqrtf(vals[0]), 1e-12f);
        float pos = 0.0f;
        #pragma unroll
        for (int m = 0; m < M_; m++) {
            float nk = fmaxf(sqrtf(vals[1 + m]), 1e-12f);
            pos += __expf(vals[5 + m] / (no * nk) * invT);
        }
        g_pos[i] = pos;
        g_denom[i] = 0.0f;
        if (i == 0) g_tile_ctr = 0;
    }

    // Quantize: 4 coalesced uint32 stores per row per thread
    #pragma unroll
    for (int r = 0; r < 5; r++) {
        const int row = r == 0 ? i : (r * B_ + i);
        uint32_t* dst = (uint32_t*)(g_fp8 + (size_t)row * D_);
        #pragma unroll
        for (int c = 0; c < 4; c++) {
            uint16_t lo = pack_e4m3x2(v[r][c].x * inv[r], v[r][c].y * inv[r]);
            uint16_t hi = pack_e4m3x2(v[r][c].z * inv[r], v[r][c].w * inv[r]);
            dst[lane + 32 * c] = (uint32_t)lo | ((uint32_t)hi << 16);
        }
    }
}

// ---------------------------------------------------------------------------
// Kernel 2: persistent FP8 (f16-acc) exp-GEMM, work-stealing over 4624 tiles.
// grid = 444 CTAs (148 SM x 3). Tile list: 32 diag + 496 upper-tri (sym,
// row+col scatter) + 4096 orig x masked. Denoms scaled by 2^-8.
// (R14/R16's proven kernel, unchanged.)
// ---------------------------------------------------------------------------
#define TILE 128
#define NCHUNK 4
#define NSTAGE 2
#define STG_A_SZ (TILE * 128)   // 16 KB
#define STG_B_SZ (TILE * 128)   // 16 KB
#define SMEM_A_OFF 1024
#define SMEM_B_OFF (SMEM_A_OFF + NSTAGE * STG_A_SZ)
#define SMEM_TOTAL (SMEM_B_OFF + NSTAGE * STG_B_SZ)   // 66560 B
#define NTILE_TOTAL (32 + 496 + 4096)                  // 4624
#define GRID_GEMM (148 * 3)

__device__ __forceinline__ void load_chunk(int chunk, int stage, uint32_t sb,
                                           const char* gA, const char* gB, int tid) {
    const int row = tid >> 1;
    const int c0 = (tid & 1) * 4;
    const char* asrc = gA + (size_t)row * D_ + chunk * 128 + c0 * 16;
    const char* bsrc = gB + (size_t)row * D_ + chunk * 128 + c0 * 16;
    const uint32_t abase = sb + SMEM_A_OFF + stage * STG_A_SZ;
    const uint32_t bbase = sb + SMEM_B_OFF + stage * STG_B_SZ;
    #pragma unroll
    for (int c = 0; c < 4; c++) {
        uint32_t off = (uint32_t)row * 128 + (c0 + c) * 16;
        CP_ASYNC16(abase + swz128(off), asrc + c * 16);
        CP_ASYNC16(bbase + swz128(off), bsrc + c * 16);
    }
}

__global__ __launch_bounds__(256, 3) void gemm_fp8_kernel(const int* __restrict__ d_iter) {
    extern __shared__ __align__(1024) char smem[];
    float* sdenom_row = (float*)smem;          // 128 floats [0,512)
    float* sdenom_col = (float*)(smem + 512);  // 128 floats [512,1024)
    uint32_t sb = smem_u32(smem);
    __shared__ int s_tile;

    const int tid  = threadIdx.x;
    const int lane = tid & 31;
    const int wid  = tid >> 5;
    const int warpM = wid & 1;
    const int warpN = wid >> 1;

    const float invT = 1.0f / get_temp(d_iter[0]);

    for (;;) {
        if (tid == 0) s_tile = atomicAdd(&g_tile_ctr, 1);
        __syncthreads();
        const int bid = s_tile;
        if (bid >= NTILE_TOTAL) break;

        // --- tile mapping ---
        int tr, tc;
        bool sym = false, diag = false;
        if (bid < 32) {                 // diagonal orig-orig tiles
            tr = bid; tc = bid; diag = true;
        } else if (bid < 528) {         // upper-triangle orig-orig (r < c)
            int k = bid - 32;
            int r = 0;
            while (k >= 31 - r) { k -= 31 - r; r++; }
            tr = r; tc = r + 1 + k;
            sym = true;
        } else {                        // orig x masked tiles
            int k = bid - 528;
            tr = k >> 7;
            tc = 32 + (k & 127);
        }
        const int rowBase = tr * TILE;
        const int colBase = tc * TILE;
        const char* gA = (const char*)(g_fp8 + (size_t)rowBase * D_);
        const char* gB = (const char*)(g_fp8 + (size_t)colBase * D_);

        if (tid < TILE) { sdenom_row[tid] = 0.0f; sdenom_col[tid] = 0.0f; }

        load_chunk(0, 0, sb, gA, gB, tid); CP_COMMIT();

        uint32_t acc[4][4][2];
        #pragma unroll
        for (int mt = 0; mt < 4; mt++)
            #pragma unroll
            for (int nt = 0; nt < 4; nt++) { acc[mt][nt][0] = 0u; acc[mt][nt][1] = 0u; }

        const int a_row = warpM * 64 + (lane & 15);
        const int a_kb  = (lane >> 4) * 16;
        const int b_row = warpN * 32 + ((lane >> 4) << 3) + (lane & 7);
        const int b_kb  = ((lane >> 3) & 1) * 16;

        #pragma unroll
        for (int k = 0; k < NCHUNK; k++) {
            asm volatile("cp.async.wait_group 0;" ::: "memory");
            __syncthreads();
            if (k + 1 < NCHUNK) {
                load_chunk(k + 1, (k + 1) & 1, sb, gA, gB, tid);
                CP_COMMIT();
            }
            const int st = k & 1;
            const uint32_t Ab = sb + SMEM_A_OFF + st * STG_A_SZ;
            const uint32_t Bb = sb + SMEM_B_OFF + st * STG_B_SZ;

            #pragma unroll
            for (int kk = 0; kk < 4; kk++) {
                uint32_t a[4][4];
                #pragma unroll
                for (int mt = 0; mt < 4; mt++) {
                    uint32_t off = (uint32_t)(a_row + mt * 16) * 128 + kk * 32 + a_kb;
                    LDMATRIX_X4(a[mt][0], a[mt][1], a[mt][2], a[mt][3], Ab + swz128(off));
                }
                uint32_t b[2][4];
                #pragma unroll
                for (int ntp = 0; ntp < 2; ntp++) {
                    uint32_t off = (uint32_t)(b_row + ntp * 16) * 128 + kk * 32 + b_kb;
                    LDMATRIX_X4(b[ntp][0], b[ntp][1], b[ntp][2], b[ntp][3], Bb + swz128(off));
                }
                #pragma unroll
                for (int mt = 0; mt < 4; mt++)
                    #pragma unroll
                    for (int nt = 0; nt < 4; nt++)
                        MMA_FP8_H(acc[mt][nt], a[mt], b[nt >> 1][(nt & 1) * 2],
                                  b[nt >> 1][(nt & 1) * 2 + 1]);
            }
        }

        // Epilogue. acc = 256*sim.
        if (!diag) {
            const __half2 kh = __float2half2_rn(invT * 1.44269504089f * (1.0f / 256.0f));
            const __half2 ch = __float2half2_rn(-8.0f);
            const __half2 zh = __float2half2_rn(0.0f);
            __half2 cs[4] = {zh, zh, zh, zh};
            #pragma unroll
            for (int mt = 0; mt < 4; mt++) {
                __half2 s0 = zh, s1 = zh;
                #pragma unroll
                for (int nt = 0; nt < 4; nt++) {
                    __half2 y0 = __hfma2(*(__half2*)&acc[mt][nt][0], kh, ch);
                    __half2 y1 = __hfma2(*(__half2*)&acc[mt][nt][1], kh, ch);
                    __half2 e0, e1;
                    *(uint32_t*)&e0 = ex2_f16x2(*(uint32_t*)&y0);
                    *(uint32_t*)&e1 = ex2_f16x2(*(uint32_t*)&y1);
                    s0 = __hadd2(s0, e0);
                    s1 = __hadd2(s1, e1);
                    if (sym) cs[nt] = __hadd2(cs[nt], __hadd2(e0, e1));
                }
                float2 f0 = __half22float2(s0);
                float2 f1 = __half22float2(s1);
                float rs0 = f0.x + f0.y;
                float rs1 = f1.x + f1.y;
                rs0 += __shfl_xor_sync(0xffffffffu, rs0, 1);
                rs0 += __shfl_xor_sync(0xffffffffu, rs0, 2);
                rs1 += __shfl_xor_sync(0xffffffffu, rs1, 1);
                rs1 += __shfl_xor_sync(0xffffffffu, rs1, 2);
                const int r0 = warpM * 64 + mt * 16 + (lane >> 2);
                if ((lane & 3) == 0) {
                    atomicAdd(&sdenom_row[r0], rs0);
                    atomicAdd(&sdenom_row[r0 + 8], rs1);
                }
            }
            if (sym) {
                #pragma unroll
                for (int nt = 0; nt < 4; nt++) {
                    uint32_t h = *(uint32_t*)&cs[nt];
                    #pragma unroll
                    for (int off = 4; off <= 16; off <<= 1) {
                        uint32_t o = __shfl_xor_sync(0xffffffffu, h, off);
                        __half2 sum = __hadd2(*(__half2*)&h, *(__half2*)&o);
                        h = *(uint32_t*)&sum;
                    }
                    if (lane < 4) {
                        float2 f = __half22float2(*(__half2*)&h);
                        const int c = warpN * 32 + nt * 8 + 2 * lane;
                        atomicAdd(&sdenom_col[c], f.x);
                        atomicAdd(&sdenom_col[c + 1], f.y);
                    }
                }
            }
        } else {
            const float sc = invT * (1.0f / 256.0f);
            const float bias = -8.0f * 0.69314718056f;
            #pragma unroll
            for (int mt = 0; mt < 4; mt++) {
                const int r0 = warpM * 64 + mt * 16 + (lane >> 2);
                const int gi0 = rowBase + r0;
                const int gi1 = gi0 + 8;
                float rs0 = 0.0f, rs1 = 0.0f;
                #pragma unroll
                for (int nt = 0; nt < 4; nt++) {
                    const int col = colBase + warpN * 32 + nt * 8 + 2 * (lane & 3);
                    float2 f01 = __half22float2(*(const __half2*)&acc[mt][nt][0]);
                    float2 f23 = __half22float2(*(const __half2*)&acc[mt][nt][1]);
                    float e0 = __expf(f01.x * sc + bias);
                    float e1 = __expf(f01.y * sc + bias);
                    float e2 = __expf(f23.x * sc + bias);
                    float e3 = __expf(f23.y * sc + bias);
                    if (col != gi0)     rs0 += e0;
                    if (col + 1 != gi0) rs0 += e1;
                    if (col != gi1)     rs1 += e2;
                    if (col + 1 != gi1) rs1 += e3;
                }
                rs0 += __shfl_xor_sync(0xffffffffu, rs0, 1);
                rs0 += __shfl_xor_sync(0xffffffffu, rs0, 2);
                rs1 += __shfl_xor_sync(0xffffffffu, rs1, 1);
                rs1 += __shfl_xor_sync(0xffffffffu, rs1, 2);
                if ((lane & 3) == 0) {
                    atomicAdd(&sdenom_row[r0], rs0);
                    atomicAdd(&sdenom_row[r0 + 8], rs1);
                }
            }
        }

        __syncthreads();
        if (tid < TILE) {
            atomicAdd(&g_denom[rowBase + tid], sdenom_row[tid]);
            if (sym) atomicAdd(&g_denom[colBase + tid], sdenom_col[tid]);
        }
        __syncthreads();   // smem accumulators reused next tile
    }
}

// ---------------------------------------------------------------------------
// Kernel 3 (fused loss+finalize): one block, 1024 threads, 4 rows each.
// g_denom holds denom * 2^-8.
// ---------------------------------------------------------------------------
__global__ __launch_bounds__(1024) void loss_finalize_kernel(float* __restrict__ out) {
    const int t = threadIdx.x;
    float loss = 0.0f;
    #pragma unroll
    for (int q = 0; q < 4; q++) {
        const int i = t + q * 1024;
        loss += logf(g_denom[i] * 256.0f + 1e-8f) - logf(g_pos[i]);
    }
    #pragma unroll
    for (int off = 16; off > 0; off >>= 1)
        loss += __shfl_down_sync(0xffffffffu, loss, off);
    __shared__ float sm[32];
    if ((t & 31) == 0) sm[t >> 5] = loss;
    __syncthreads();
    if (t < 32) {
        float v = sm[t];
        #pragma unroll
        for (int off = 16; off > 0; off >>= 1)
            v += __shfl_down_sync(0xffffffffu, v, off);
        if (t == 0) out[0] = v * (1.0f / (float)B_);
    }
}

// ---------------------------------------------------------------------------
extern "C" void kernel_launch(void* const* d_in, const int* in_sizes, int n_in,
                              void* d_out, int out_size) {
    const float* orig   = (const float*)d_in[0];
    const float* masked = (const float*)d_in[1];
    const int*   iter   = (const int*)d_in[2];
    float* out = (float*)d_out;

    cudaFuncSetAttribute(gemm_fp8_kernel,
                         cudaFuncAttributeMaxDynamicSharedMemorySize, SMEM_TOTAL);

    prep_kernel<<<B_ / 8, 256>>>(orig, masked, iter);
    gemm_fp8_kernel<<<GRID_GEMM, 256, SMEM_TOTAL>>>(iter);
    loss_finalize_kernel<<<1, 1024>>>(out);
}